// round 1
// baseline (speedup 1.0000x reference)
#include <cuda_runtime.h>
#include <math_constants.h>

#define NQ 32768
#define NM 2048
#define ND 512

typedef unsigned long long u64;

// 256 MB score scratch (static __device__ global: the sanctioned scratch path)
__device__ float g_S[(size_t)NQ * NM];

#define FMA2(acc, a, b) \
    asm volatile("fma.rn.f32x2 %0, %1, %2, %0;" : "+l"(acc) : "l"(a), "l"(b))

// ---------------------------------------------------------------------------
// Kernel 1: S = Q @ M^T   (NT gemm, both operands K-major, fp32 via f32x2 FFMA)
// Tile: BM=128, BN=128, BK=16, 256 threads, 8x8 per thread (4 f32x2 col-pairs)
// ---------------------------------------------------------------------------
__global__ __launch_bounds__(256, 2)
void gemm_kernel(const float* __restrict__ A, const float* __restrict__ B) {
    __shared__ float As[16][128];
    __shared__ float Bs[16][128];

    const int tid  = threadIdx.x;
    const int row0 = blockIdx.y * 128;
    const int col0 = blockIdx.x * 128;
    const int tx   = tid & 15;
    const int ty   = tid >> 4;
    const int trow = ty * 8;
    const int tcol = tx * 8;

    u64 acc[8][4];
#pragma unroll
    for (int i = 0; i < 8; i++)
#pragma unroll
        for (int j = 0; j < 4; j++) acc[i][j] = 0ULL;

    const float4* A4 = reinterpret_cast<const float4*>(A + (size_t)row0 * ND);
    const float4* B4 = reinterpret_cast<const float4*>(B + (size_t)col0 * ND);

    for (int k0 = 0; k0 < ND; k0 += 16) {
        // load A-tile (128x16) and B-tile (128x16), stored transposed [k][m]
#pragma unroll
        for (int i = 0; i < 2; i++) {
            int id = tid + i * 256;          // 0..511 float4 slots
            int r  = id >> 2;                // row in tile 0..127
            int kc = (id & 3) << 2;          // k offset 0,4,8,12
            float4 av = A4[(size_t)r * (ND / 4) + ((k0 + kc) >> 2)];
            As[kc + 0][r] = av.x; As[kc + 1][r] = av.y;
            As[kc + 2][r] = av.z; As[kc + 3][r] = av.w;
            float4 bv = B4[(size_t)r * (ND / 4) + ((k0 + kc) >> 2)];
            Bs[kc + 0][r] = bv.x; Bs[kc + 1][r] = bv.y;
            Bs[kc + 2][r] = bv.z; Bs[kc + 3][r] = bv.w;
        }
        __syncthreads();

#pragma unroll
        for (int k = 0; k < 16; k++) {
            float4 a0 = *reinterpret_cast<const float4*>(&As[k][trow]);
            float4 a1 = *reinterpret_cast<const float4*>(&As[k][trow + 4]);
            float4 b0 = *reinterpret_cast<const float4*>(&Bs[k][tcol]);
            float4 b1 = *reinterpret_cast<const float4*>(&Bs[k][tcol + 4]);
            float av[8] = {a0.x, a0.y, a0.z, a0.w, a1.x, a1.y, a1.z, a1.w};
            float bv[8] = {b0.x, b0.y, b0.z, b0.w, b1.x, b1.y, b1.z, b1.w};
            u64 ap[8], bp[4];
#pragma unroll
            for (int i = 0; i < 8; i++) {
                unsigned int u = __float_as_uint(av[i]);
                asm("mov.b64 %0, {%1, %1};" : "=l"(ap[i]) : "r"(u));
            }
#pragma unroll
            for (int j = 0; j < 4; j++) {
                asm("mov.b64 %0, {%1, %2};" : "=l"(bp[j])
                    : "r"(__float_as_uint(bv[2 * j])),
                      "r"(__float_as_uint(bv[2 * j + 1])));
            }
#pragma unroll
            for (int i = 0; i < 8; i++)
#pragma unroll
                for (int j = 0; j < 4; j++) FMA2(acc[i][j], ap[i], bp[j]);
        }
        __syncthreads();
    }

    // store 8x8 tile (f32x2 pairs are little-endian: low word = even column)
    float* C = g_S + (size_t)(row0 + trow) * NM + (col0 + tcol);
#pragma unroll
    for (int i = 0; i < 8; i++) {
        u64* cp = reinterpret_cast<u64*>(C + (size_t)i * NM);
#pragma unroll
        for (int j = 0; j < 4; j++) cp[j] = acc[i][j];
    }
}

// ---------------------------------------------------------------------------
// Kernel 2: per query row — softmax stats, top-10 (index tie-break to lower,
// matching jax.lax.top_k), split-5 re-softmax, gather, blend.
// One CTA (256 threads) per row.
// ---------------------------------------------------------------------------
__global__ __launch_bounds__(256)
void rowpass_kernel(const float* __restrict__ Q, const float* __restrict__ Mi,
                    float* __restrict__ out) {
    __shared__ float s[NM];
    __shared__ float rbuf[8];
    __shared__ int   ribuf[8];
    __shared__ float pv[10];
    __shared__ int   pidx[10];
    __shared__ float mxsh, zsh;

    const int tid = threadIdx.x;
    const int row = blockIdx.x;
    const float* srow = g_S + (size_t)row * NM;

    // load scores, row max
    float lmax = -CUDART_INF_F;
    for (int i = tid; i < NM; i += 256) {
        float v = srow[i];
        s[i] = v;
        lmax = fmaxf(lmax, v);
    }
#pragma unroll
    for (int o = 16; o; o >>= 1)
        lmax = fmaxf(lmax, __shfl_xor_sync(0xffffffffu, lmax, o));
    if ((tid & 31) == 0) rbuf[tid >> 5] = lmax;
    __syncthreads();
    if (tid == 0) {
        float m = rbuf[0];
        for (int w = 1; w < 8; w++) m = fmaxf(m, rbuf[w]);
        mxsh = m;
    }
    __syncthreads();
    const float mx = mxsh;

    // sum of exp
    float lsum = 0.f;
    for (int i = tid; i < NM; i += 256) lsum += expf(s[i] - mx);
#pragma unroll
    for (int o = 16; o; o >>= 1)
        lsum += __shfl_xor_sync(0xffffffffu, lsum, o);
    __syncthreads();                       // rbuf reuse barrier
    if ((tid & 31) == 0) rbuf[tid >> 5] = lsum;
    __syncthreads();
    if (tid == 0) {
        float z = 0.f;
        for (int w = 0; w < 8; w++) z += rbuf[w];
        zsh = z;
    }
    // (zsh consumed after the pick loop; its syncs cover visibility)

    // iterative top-10 with tie-break to lowest index
    for (int t = 0; t < 10; t++) {
        float bv = -CUDART_INF_F;
        int   bi = 0x7fffffff;
        for (int i = tid; i < NM; i += 256) {
            float v = s[i];
            if (v > bv) { bv = v; bi = i; }   // ascending scan keeps lowest idx
        }
#pragma unroll
        for (int o = 16; o; o >>= 1) {
            float ov = __shfl_xor_sync(0xffffffffu, bv, o);
            int   oi = __shfl_xor_sync(0xffffffffu, bi, o);
            if (ov > bv || (ov == bv && oi < bi)) { bv = ov; bi = oi; }
        }
        __syncthreads();
        if ((tid & 31) == 0) { rbuf[tid >> 5] = bv; ribuf[tid >> 5] = bi; }
        __syncthreads();
        if (tid == 0) {
            float fv = rbuf[0]; int fi = ribuf[0];
            for (int w = 1; w < 8; w++) {
                if (rbuf[w] > fv || (rbuf[w] == fv && ribuf[w] < fi)) {
                    fv = rbuf[w]; fi = ribuf[w];
                }
            }
            pv[t] = fv; pidx[t] = fi;
            s[fi] = -CUDART_INF_F;           // remove for next pick
        }
        __syncthreads();
    }

    const float Z = zsh;

    // per-group softmax weights (computed redundantly in every thread; cheap)
    float wt[5], wb[5];
    {
        float p[10];
#pragma unroll
        for (int j = 0; j < 10; j++) p[j] = expf(pv[j] - mx) / Z;
        float st = 0.f, sb = 0.f;
#pragma unroll
        for (int j = 0; j < 5; j++) { wt[j] = expf(p[j] - p[0]);     st += wt[j]; }
#pragma unroll
        for (int j = 0; j < 5; j++) { wb[j] = expf(p[5 + j] - p[5]); sb += wb[j]; }
#pragma unroll
        for (int j = 0; j < 5; j++) { wt[j] /= st; wb[j] /= sb; }
    }
    int idx[10];
#pragma unroll
    for (int j = 0; j < 10; j++) idx[j] = pidx[j];

    // gather + blend
    for (int d = tid; d < ND; d += 256) {
        float top = 0.f, bot = 0.f;
#pragma unroll
        for (int j = 0; j < 5; j++) top += wt[j] * Mi[(size_t)idx[j] * ND + d];
#pragma unroll
        for (int j = 0; j < 5; j++) bot += wb[j] * Mi[(size_t)idx[5 + j] * ND + d];
        float q = Q[(size_t)row * ND + d];
        out[(size_t)row * ND + d]                    = 0.5f  * q + 0.5f  * top;
        out[(size_t)NQ * ND + (size_t)row * ND + d]  = 0.01f * q + 0.99f * bot;
    }
}

// ---------------------------------------------------------------------------
extern "C" void kernel_launch(void* const* d_in, const int* in_sizes, int n_in,
                              void* d_out, int out_size) {
    const float* Q  = (const float*)d_in[0];
    const float* Mi = (const float*)d_in[1];
    // defensive: identify operands by size (query = NQ*ND, m_items = NM*ND)
    if (n_in >= 2 && in_sizes[0] == NM * ND && in_sizes[1] == NQ * ND) {
        const float* t = Q; Q = Mi; Mi = t;
    }
    float* out = (float*)d_out;

    dim3 ggrid(NM / 128, NQ / 128);      // (16, 256)
    gemm_kernel<<<ggrid, 256>>>(Q, Mi);
    rowpass_kernel<<<NQ, 256>>>(Q, Mi, out);
}

// round 3
// speedup vs baseline: 2.0195x; 2.0195x over previous
#include <cuda_runtime.h>
#include <cuda_bf16.h>
#include <math_constants.h>
#include <cstdint>

#define NQ 32768
#define NM 2048
#define ND 512
#define BM 128
#define BN 128
#define BK 32
#define KTILES (ND / BK)          // 16
#define BKP 40                    // padded k-stride (bf16 elems) -> 80B rows
#define STAGE_ELEMS (128 * BKP)   // 5120 bf16 = 10240 B per operand stage
#define STAGE_BYTES (STAGE_ELEMS * 2)
#define NSTAGE 3
#define SMEM_GEMM (2 * NSTAGE * STAGE_BYTES)   // 61440

// __device__ globals = sanctioned scratch
__device__ float          g_S[(size_t)NQ * NM];    // 256 MB bf16-accurate scores
__device__ __nv_bfloat16  g_Ab[(size_t)NQ * ND];   //  32 MB
__device__ __nv_bfloat16  g_Bb[(size_t)NM * ND];   //   2 MB

__device__ __forceinline__ uint32_t smem_u32(const void* p) {
    uint32_t a;
    asm("{ .reg .u64 t; cvta.to.shared.u64 t, %1; cvt.u32.u64 %0, t; }"
        : "=r"(a) : "l"(p));
    return a;
}
#define CP16(dst, src) \
    asm volatile("cp.async.cg.shared.global [%0], [%1], 16;" \
                 :: "r"(dst), "l"(src) : "memory")
#define CP_COMMIT() asm volatile("cp.async.commit_group;" ::: "memory")
#define CP_WAIT1()  asm volatile("cp.async.wait_group 1;" ::: "memory")

#define LDMX4(r0, r1, r2, r3, addr) \
    asm volatile("ldmatrix.sync.aligned.m8n8.x4.shared.b16 {%0,%1,%2,%3}, [%4];" \
                 : "=r"(r0), "=r"(r1), "=r"(r2), "=r"(r3) : "r"(addr))

#define MMA16816(c, a, b0, b1) \
    asm volatile("mma.sync.aligned.m16n8k16.row.col.f32.bf16.bf16.f32 " \
                 "{%0,%1,%2,%3}, {%4,%5,%6,%7}, {%8,%9}, {%0,%1,%2,%3};" \
                 : "+f"((c)[0]), "+f"((c)[1]), "+f"((c)[2]), "+f"((c)[3]) \
                 : "r"((a)[0]), "r"((a)[1]), "r"((a)[2]), "r"((a)[3]),   \
                   "r"(b0), "r"(b1))

// ---------------------------------------------------------------------------
__global__ void tobf16_kernel(const float* __restrict__ X,
                              __nv_bfloat16* __restrict__ Y, int total) {
    int i = blockIdx.x * 256 + threadIdx.x;
    if (i < total) Y[i] = __float2bfloat16(X[i]);
}

// ---------------------------------------------------------------------------
// HMMA GEMM: g_S = Ab @ Bb^T, both K-major. 128x128 tile, BK=32, 3-stage
// cp.async pipeline, 8 warps in 4(M)x2(N) grid, warp tile 32x64.
// ---------------------------------------------------------------------------
__device__ __forceinline__ void load_stage(uint32_t aBase, uint32_t bBase,
                                           int buf, int kt, int row0, int col0,
                                           int tid) {
#pragma unroll
    for (int i = 0; i < 2; i++) {
        int id = tid + (i << 8);          // 0..511
        int r  = id >> 2;
        int kc = (id & 3) << 3;
        uint32_t da = aBase + buf * STAGE_BYTES + (uint32_t)(r * BKP + kc) * 2;
        const __nv_bfloat16* ga = g_Ab + (size_t)(row0 + r) * ND + kt * BK + kc;
        CP16(da, ga);
        uint32_t db = bBase + buf * STAGE_BYTES + (uint32_t)(r * BKP + kc) * 2;
        const __nv_bfloat16* gb = g_Bb + (size_t)(col0 + r) * ND + kt * BK + kc;
        CP16(db, gb);
    }
}

__global__ __launch_bounds__(256)
void gemm_hmma() {
    extern __shared__ __nv_bfloat16 sm[];
    const int tid = threadIdx.x, lane = tid & 31, wid = tid >> 5;
    const int row0 = blockIdx.y * BM, col0 = blockIdx.x * BN;
    const int mw = (wid >> 1) * 32;   // warp m offset
    const int nw = (wid & 1) * 64;    // warp n offset
    uint32_t aBase = smem_u32(sm);
    uint32_t bBase = aBase + NSTAGE * STAGE_BYTES;

    // ldmatrix lane address components
    const int a_row = lane & 15;
    const int a_k8  = (lane >> 4) << 3;
    const int b_row = (lane & 7) + ((lane >> 4) << 3);
    const int b_k8  = ((lane >> 3) & 1) << 3;

    float c[2][8][4];
#pragma unroll
    for (int mt = 0; mt < 2; mt++)
#pragma unroll
        for (int nt = 0; nt < 8; nt++)
#pragma unroll
            for (int r = 0; r < 4; r++) c[mt][nt][r] = 0.f;

    load_stage(aBase, bBase, 0, 0, row0, col0, tid); CP_COMMIT();
    load_stage(aBase, bBase, 1, 1, row0, col0, tid); CP_COMMIT();

    for (int s = 0; s < KTILES; s++) {
        if (s + 2 < KTILES)
            load_stage(aBase, bBase, (s + 2) % NSTAGE, s + 2, row0, col0, tid);
        CP_COMMIT();
        CP_WAIT1();
        __syncthreads();

        const int buf = s % NSTAGE;
#pragma unroll
        for (int k16 = 0; k16 < BK; k16 += 16) {
            uint32_t a[2][4], b[4][4];
#pragma unroll
            for (int mt = 0; mt < 2; mt++) {
                uint32_t addr = aBase + buf * STAGE_BYTES +
                    (uint32_t)((mw + mt * 16 + a_row) * BKP + k16 + a_k8) * 2;
                LDMX4(a[mt][0], a[mt][1], a[mt][2], a[mt][3], addr);
            }
#pragma unroll
            for (int np = 0; np < 4; np++) {
                uint32_t addr = bBase + buf * STAGE_BYTES +
                    (uint32_t)((nw + np * 16 + b_row) * BKP + k16 + b_k8) * 2;
                LDMX4(b[np][0], b[np][1], b[np][2], b[np][3], addr);
            }
#pragma unroll
            for (int mt = 0; mt < 2; mt++)
#pragma unroll
                for (int nt = 0; nt < 8; nt++)
                    MMA16816(c[mt][nt], a[mt],
                             b[nt >> 1][(nt & 1) * 2],
                             b[nt >> 1][(nt & 1) * 2 + 1]);
        }
        __syncthreads();
    }

    // epilogue: fp32 scores to g_S
#pragma unroll
    for (int mt = 0; mt < 2; mt++) {
        int r0r = row0 + mw + mt * 16 + (lane >> 2);
#pragma unroll
        for (int nt = 0; nt < 8; nt++) {
            int col = col0 + nw + nt * 8 + (lane & 3) * 2;
            float2 v0 = make_float2(c[mt][nt][0], c[mt][nt][1]);
            float2 v1 = make_float2(c[mt][nt][2], c[mt][nt][3]);
            *reinterpret_cast<float2*>(&g_S[(size_t)r0r * NM + col])       = v0;
            *reinterpret_cast<float2*>(&g_S[(size_t)(r0r + 8) * NM + col]) = v1;
        }
    }
}

// ---------------------------------------------------------------------------
// Rowpass: approx top-16 (register tournament) -> exact fp32 rescore ->
// true top-10 -> softmax weights -> gather + blend.  One CTA per row.
// ---------------------------------------------------------------------------
__global__ __launch_bounds__(256)
void rowpass_kernel(const float* __restrict__ Q, const float* __restrict__ Mi,
                    float* __restrict__ out) {
    __shared__ float qs[ND];
    __shared__ float wv[8][16];
    __shared__ int   wi[8][16];
    __shared__ float ssum[8];
    __shared__ float cv[16];
    __shared__ int   ci[16];
    __shared__ float ce[16];
    __shared__ float selv[10];
    __shared__ int   seli[10];
    __shared__ float zsh;

    const int tid = threadIdx.x, lane = tid & 31, wid = tid >> 5;
    const int row = blockIdx.x;
    const float* srow = g_S + (size_t)row * NM;

    for (int d = tid; d < ND; d += 256) qs[d] = Q[(size_t)row * ND + d];

    float v[8]; int ixr[8]; float lsum = 0.f;
#pragma unroll
    for (int j = 0; j < 8; j++) {
        int i = tid + (j << 8);
        float x = srow[i];
        v[j] = x; ixr[j] = i;
        lsum += expf(x);
    }
#pragma unroll
    for (int o = 16; o; o >>= 1) lsum += __shfl_xor_sync(~0u, lsum, o);
    if (lane == 0) ssum[wid] = lsum;

    // warp-local top-16 (each warp owns 256 scores)
    float rv[16]; int ri[16];
#pragma unroll
    for (int t = 0; t < 16; t++) {
        float bv = v[0]; int bi = ixr[0];
#pragma unroll
        for (int j = 1; j < 8; j++)
            if (v[j] > bv) { bv = v[j]; bi = ixr[j]; }   // strict > keeps low idx
#pragma unroll
        for (int o = 16; o; o >>= 1) {
            float ov = __shfl_xor_sync(~0u, bv, o);
            int   oi = __shfl_xor_sync(~0u, bi, o);
            if (ov > bv || (ov == bv && oi < bi)) { bv = ov; bi = oi; }
        }
        rv[t] = bv; ri[t] = bi;
#pragma unroll
        for (int j = 0; j < 8; j++)
            if (ixr[j] == bi) v[j] = -CUDART_INF_F;
    }
    if (lane == 0) {
#pragma unroll
        for (int t = 0; t < 16; t++) { wv[wid][t] = rv[t]; wi[wid][t] = ri[t]; }
    }
    __syncthreads();

    // warp 0: merge 8 sorted 16-lists -> global approx top-16; Z partial sum
    if (wid == 0) {
        int p = 0;
        float hv = (lane < 8) ? wv[lane][0] : -CUDART_INF_F;
        int   hi = (lane < 8) ? wi[lane][0] : 0x7fffffff;
        for (int t = 0; t < 16; t++) {
            float bv = hv; int bi = hi;
#pragma unroll
            for (int o = 16; o; o >>= 1) {
                float ov = __shfl_xor_sync(~0u, bv, o);
                int   oi = __shfl_xor_sync(~0u, bi, o);
                if (ov > bv || (ov == bv && oi < bi)) { bv = ov; bi = oi; }
            }
            if (lane == 0) { cv[t] = bv; ci[t] = bi; }
            if (lane < 8 && hi == bi) {
                p++;
                hv = (p < 16) ? wv[lane][p] : -CUDART_INF_F;
                hi = (p < 16) ? wi[lane][p] : 0x7fffffff;
            }
        }
        float z = (lane < 8) ? ssum[lane] : 0.f;
#pragma unroll
        for (int o = 16; o; o >>= 1) z += __shfl_xor_sync(~0u, z, o);
        if (lane == 0) zsh = z;
    }
    __syncthreads();

    // exact fp32 rescore of the 16 candidates (warp w -> candidates w, w+8)
    const float4* q4 = reinterpret_cast<const float4*>(qs);
#pragma unroll
    for (int rep = 0; rep < 2; rep++) {
        int c = wid + rep * 8;
        const float4* m4 = reinterpret_cast<const float4*>(Mi + (size_t)ci[c] * ND);
        float acc = 0.f;
#pragma unroll
        for (int it = 0; it < 4; it++) {
            int d = lane + it * 32;
            float4 a = q4[d], b = m4[d];
            acc += a.x * b.x + a.y * b.y + a.z * b.z + a.w * b.w;
        }
#pragma unroll
        for (int o = 16; o; o >>= 1) acc += __shfl_xor_sync(~0u, acc, o);
        if (lane == 0) ce[c] = acc;
    }
    __syncthreads();

    // rank the 16 exact scores (stable by index), take top-10; correct Z
    if (wid == 0) {
        float e = (lane < 16) ? ce[lane] : 0.f;
        int  ii = (lane < 16) ? ci[lane] : 0;
        if (lane < 16) {
            int rank = 0;
#pragma unroll
            for (int j = 0; j < 16; j++) {
                float ej = ce[j]; int ij = ci[j];
                rank += (ej > e) || (ej == e && ij < ii);
            }
            if (rank < 10) { selv[rank] = e; seli[rank] = ii; }
        }
        float dz = (lane < 16) ? (expf(e) - expf(cv[lane])) : 0.f;
#pragma unroll
        for (int o = 16; o; o >>= 1) dz += __shfl_xor_sync(~0u, dz, o);
        if (lane == 0) zsh += dz;
    }
    __syncthreads();

    const float Z = zsh;
    float p10[10];
#pragma unroll
    for (int j = 0; j < 10; j++) p10[j] = expf(selv[j]) / Z;
    float wt[5], wb[5], st = 0.f, sb = 0.f;
#pragma unroll
    for (int j = 0; j < 5; j++) { wt[j] = expf(p10[j]     - p10[0]); st += wt[j]; }
#pragma unroll
    for (int j = 0; j < 5; j++) { wb[j] = expf(p10[5 + j] - p10[5]); sb += wb[j]; }
    const float rst = 1.f / st, rsb = 1.f / sb;
    int id[10];
#pragma unroll
    for (int j = 0; j < 10; j++) id[j] = seli[j];

    for (int d = tid; d < ND; d += 256) {
        float top = 0.f, bot = 0.f;
#pragma unroll
        for (int j = 0; j < 5; j++) top += wt[j] * Mi[(size_t)id[j] * ND + d];
#pragma unroll
        for (int j = 0; j < 5; j++) bot += wb[j] * Mi[(size_t)id[5 + j] * ND + d];
        top *= rst; bot *= rsb;
        float q = qs[d];
        out[(size_t)row * ND + d]                   = 0.5f  * q + 0.5f  * top;
        out[(size_t)NQ * ND + (size_t)row * ND + d] = 0.01f * q + 0.99f * bot;
    }
}

// ---------------------------------------------------------------------------
extern "C" void kernel_launch(void* const* d_in, const int* in_sizes, int n_in,
                              void* d_out, int out_size) {
    const float* Q  = (const float*)d_in[0];
    const float* Mi = (const float*)d_in[1];
    if (n_in >= 2 && in_sizes[0] == NM * ND && in_sizes[1] == NQ * ND) {
        const float* t = Q; Q = Mi; Mi = t;
    }
    float* out = (float*)d_out;

    static int attr_done = 0;
    if (!attr_done) {
        cudaFuncSetAttribute(gemm_hmma,
                             cudaFuncAttributeMaxDynamicSharedMemorySize,
                             SMEM_GEMM);
        attr_done = 1;
    }

    __nv_bfloat16* gA;  cudaGetSymbolAddress((void**)&gA, g_Ab);
    __nv_bfloat16* gB;  cudaGetSymbolAddress((void**)&gB, g_Bb);
    tobf16_kernel<<<(NQ * ND + 255) / 256, 256>>>(Q,  gA, NQ * ND);
    tobf16_kernel<<<(NM * ND + 255) / 256, 256>>>(Mi, gB, NM * ND);

    dim3 gg(NM / BN, NQ / BM);   // (16, 256)
    gemm_hmma<<<gg, 256, SMEM_GEMM>>>();
    rowpass_kernel<<<NQ, 256>>>(Q, Mi, out);
}